// round 10
// baseline (speedup 1.0000x reference)
#include <cuda_runtime.h>
#include <cuda_fp16.h>
#include <cstdint>

#define HID   512
#define SRC   2048
#define BATCH 64

// main kernel tiling: CTA tile M=128, N=128, K=512 in 16 KC=32 stages
#define KC        32
#define A32_SLOT  16384                  // 128 rows x 32 fp32, 128B/row, 16B-unit swizzled
#define A16_SLOT  10240                  // 128 rows x 32 fp16, 80B stride (64B data + 16B pad)
#define B_SLOT    10240                  // 128 rows x 32 fp16, 80B stride
#define OFF_A32   0                      // 3 slots: 49152
#define OFF_A16   49152                  // 2 slots: 20480
#define OFF_B     69632                  // 4 slots: 40960
#define SMEM_BYTES 110592                // 108 KB -> 2 CTAs/SM

// ---------------- device scratch (static, no runtime allocation) ----------------
__device__ __align__(16) __half g_W1h[HID * HID];
__device__ float g_cbias[BATCH * HID];          // W1_b + W2_b + h@W2^T
__device__ float g_part[4][BATCH][SRC];         // per-n-block partial scores

// ---------------- helpers ----------------
__device__ __forceinline__ unsigned smem_u32(const void* p) {
    return (unsigned)__cvta_generic_to_shared(p);
}
__device__ __forceinline__ void ldsm4(uint32_t r[4], unsigned addr) {
    asm volatile("ldmatrix.sync.aligned.m8n8.x4.shared.b16 {%0,%1,%2,%3}, [%4];"
                 : "=r"(r[0]), "=r"(r[1]), "=r"(r[2]), "=r"(r[3]) : "r"(addr));
}
__device__ __forceinline__ void mma_fp16(float c[4], const uint32_t a[4], const uint32_t b[2]) {
    asm volatile(
        "mma.sync.aligned.m16n8k16.row.col.f32.f16.f16.f32 "
        "{%0,%1,%2,%3}, {%4,%5,%6,%7}, {%8,%9}, {%0,%1,%2,%3};"
        : "+f"(c[0]), "+f"(c[1]), "+f"(c[2]), "+f"(c[3])
        : "r"(a[0]), "r"(a[1]), "r"(a[2]), "r"(a[3]), "r"(b[0]), "r"(b[1]));
}
__device__ __forceinline__ void cp_async16(uint32_t dst, const void* src) {
    asm volatile("cp.async.cg.shared.global [%0], [%1], 16;" :: "r"(dst), "l"(src) : "memory");
}
__device__ __forceinline__ void cp_commit() {
    asm volatile("cp.async.commit_group;" ::: "memory");
}
__device__ __forceinline__ uint32_t packh2(float a, float b) {
    __half2 h = __floats2half2_rn(a, b);
    return *reinterpret_cast<uint32_t*>(&h);
}

// ---------------- kernel 1: convert W1 -> fp16 ----------------
__global__ void prep_w_kernel(const float* __restrict__ W1w) {
    int i = blockIdx.x * blockDim.x + threadIdx.x;
    if (i < HID * HID) g_W1h[i] = __float2half_rn(W1w[i]);
}

// ---------------- kernel 2: cbias[b][o] = W1_b[o] + W2_b[o] + h[b]@W2[o] ----------------
__global__ void cbias_kernel(const float* __restrict__ h,
                             const float* __restrict__ W2w,
                             const float* __restrict__ W2b,
                             const float* __restrict__ W1b) {
    __shared__ float hs[HID];
    const int b = blockIdx.x;
    const int o = blockIdx.y * 128 + threadIdx.x;
    for (int k = threadIdx.x; k < HID; k += 128) hs[k] = h[b * HID + k];
    __syncthreads();
    float acc = W2b[o] + W1b[o];
    const float* wr = W2w + o * HID;
#pragma unroll 8
    for (int k = 0; k < HID; k++) acc += hs[k] * wr[k];
    g_cbias[b * HID + o] = acc;
}

// ---------------- kernel 3: deep-pipelined fused cvt + fp16 GEMM + tanh + V-dot ----------------
// grid (4 nb, 16 st, 64 b); 256 threads = 8 warps (4 along M x 2 along N).
// Schedule per iter: load G(it+3) | wait | convert(it+1) | compute(it) | sync.
__global__ __launch_bounds__(256, 2) void attn_main_kernel(const float* __restrict__ enc,
                                                           const float* __restrict__ Vw) {
    extern __shared__ __align__(128) char smem[];
    const uint32_t sb = smem_u32(smem);

    const int nb  = blockIdx.x;          // n-block fastest -> 4 CTAs share enc tile via L2
    const int st  = blockIdx.y;
    const int b   = blockIdx.z;
    const int tid = threadIdx.x;
    const int lane = tid & 31;
    const int wid  = tid >> 5;
    const int warp_m = wid & 3;
    const int warp_n = wid >> 2;
    const int s0 = st * 128;
    const int o0 = nb * 128;

    const float* encRow = enc + (size_t)(b * SRC + s0) * HID;

    float acc[2][8][4];
#pragma unroll
    for (int i = 0; i < 2; i++)
#pragma unroll
        for (int j = 0; j < 8; j++)
#pragma unroll
            for (int r = 0; r < 4; r++) acc[i][j][r] = 0.f;

    // ---- gmem stage loader: A fp32 (swizzled units) + B fp16 (80B stride) ----
    auto load_gmem = [&](int stage) {
        const int kc = stage * KC;
        const uint32_t a32 = sb + OFF_A32 + (stage % 3) * A32_SLOT;
#pragma unroll
        for (int k = 0; k < 4; ++k) {
            const int q = tid + k * 256;          // 16B unit, 0..1023
            const int row = q >> 3;
            const int u   = q & 7;                // 4-float unit
            cp_async16(a32 + row * 128 + ((u ^ (row & 7)) << 4),
                       encRow + (size_t)row * HID + kc + u * 4);
        }
        const uint32_t bb = sb + OFF_B + (stage & 3) * B_SLOT;
#pragma unroll
        for (int k = 0; k < 2; ++k) {
            const int p = tid + k * 256;          // 16B unit, 0..511
            const int row = p >> 2;
            const int u   = p & 3;                // 8-half unit
            cp_async16(bb + row * 80 + u * 16,
                       g_W1h + (size_t)(o0 + row) * HID + kc + u * 8);
        }
        cp_commit();
    };

    // ---- convert stage fp32 smem -> fp16 smem (80B-stride rows) ----
    auto convert_stage = [&](int stage) {
        const char* a32 = smem + OFF_A32 + (stage % 3) * A32_SLOT;
        char* a16 = smem + OFF_A16 + (stage & 1) * A16_SLOT;
        const int row = tid >> 1;
        const int h   = tid & 1;
#pragma unroll
        for (int m = 0; m < 2; ++m) {
            const int ua = h * 4 + 2 * m;
            const float4 f0 = *reinterpret_cast<const float4*>(
                a32 + row * 128 + ((ua ^ (row & 7)) << 4));
            const float4 f1 = *reinterpret_cast<const float4*>(
                a32 + row * 128 + (((ua + 1) ^ (row & 7)) << 4));
            uint4 v;
            v.x = packh2(f0.x, f0.y);
            v.y = packh2(f0.z, f0.w);
            v.z = packh2(f1.x, f1.y);
            v.w = packh2(f1.z, f1.w);
            *reinterpret_cast<uint4*>(a16 + row * 80 + h * 32 + m * 16) = v;
        }
    };

    // ---- stage compute: 2 k16 steps ----
    auto compute_stage = [&](int stage) {
        const uint32_t a16 = sb + OFF_A16 + (stage & 1) * A16_SLOT;
        const uint32_t bb  = sb + OFF_B + (stage & 3) * B_SLOT;
#pragma unroll
        for (int ks = 0; ks < KC; ks += 16) {
            uint32_t a[2][4];
#pragma unroll
            for (int mt = 0; mt < 2; mt++) {
                const int r = warp_m * 32 + mt * 16 + (lane & 15);
                const int u = (ks >> 3) + (lane >> 4);
                ldsm4(a[mt], a16 + r * 80 + u * 16);
            }
#pragma unroll
            for (int ntp = 0; ntp < 4; ntp++) {
                const int br = warp_n * 64 + ntp * 16 + ((lane >> 4) << 3) + (lane & 7);
                const int bu = (ks >> 3) + ((lane >> 3) & 1);
                uint32_t bh[4];
                ldsm4(bh, bb + br * 80 + bu * 16);
#pragma unroll
                for (int mt = 0; mt < 2; mt++) {
#pragma unroll
                    for (int half = 0; half < 2; half++) {
                        mma_fp16(acc[mt][ntp * 2 + half], a[mt], bh + 2 * half);
                    }
                }
            }
        }
    };

    // ---- prologue ----
    load_gmem(0);
    load_gmem(1);
    load_gmem(2);
    asm volatile("cp.async.wait_group 1;" ::: "memory");   // G0, G1 complete
    __syncthreads();                                       // visible to all
    convert_stage(0);
    __syncthreads();                                       // A16[0] ready

    // ---- mainloop: 16 stages, one sync each ----
#pragma unroll 1
    for (int it = 0; it < 16; ++it) {
        if (it < 13) {
            load_gmem(it + 3);
            asm volatile("cp.async.wait_group 1;" ::: "memory");  // G(it+2) done (per-thread)
        } else if (it == 13) {
            asm volatile("cp.async.wait_group 0;" ::: "memory");  // G15 done
        }
        if (it < 15) convert_stage(it + 1);   // A32(it+1) was waited+synced last iter
        compute_stage(it);                    // A16[it&1], B[it&3] ready since last sync
        __syncthreads();
    }

    // ---- epilogue: tanh(acc + cbias) * V, reduce over the 128 o-columns ----
    float rowsum[2][2];
    rowsum[0][0] = rowsum[0][1] = rowsum[1][0] = rowsum[1][1] = 0.f;

    const float* cbRow = g_cbias + b * HID;
#pragma unroll
    for (int nt = 0; nt < 8; nt++) {
        const int o = o0 + warp_n * 64 + nt * 8 + (lane & 3) * 2;
        const float cb0 = cbRow[o],     v0 = Vw[o];
        const float cb1 = cbRow[o + 1], v1 = Vw[o + 1];
#pragma unroll
        for (int mt = 0; mt < 2; mt++) {
            rowsum[mt][0] += tanhf(acc[mt][nt][0] + cb0) * v0;
            rowsum[mt][0] += tanhf(acc[mt][nt][1] + cb1) * v1;
            rowsum[mt][1] += tanhf(acc[mt][nt][2] + cb0) * v0;
            rowsum[mt][1] += tanhf(acc[mt][nt][3] + cb1) * v1;
        }
    }

    float* sRed = reinterpret_cast<float*>(smem);   // alias A32 region (all reads done)
#pragma unroll
    for (int mt = 0; mt < 2; mt++) {
#pragma unroll
        for (int j = 0; j < 2; j++) {
            float v = rowsum[mt][j];
            v += __shfl_xor_sync(0xffffffffu, v, 1);
            v += __shfl_xor_sync(0xffffffffu, v, 2);
            if ((lane & 3) == 0) {
                const int row = warp_m * 32 + mt * 16 + (lane >> 2) + 8 * j;
                sRed[row * 2 + warp_n] = v;
            }
        }
    }
    __syncthreads();

    if (tid < 128) {
        g_part[nb][b][s0 + tid] = sRed[tid * 2] + sRed[tid * 2 + 1];
    }
}

// ---------------- kernel 4: sum partials + softmax over S ----------------
__global__ void softmax_kernel(float* __restrict__ out) {
    __shared__ float sv[SRC];
    __shared__ float red[256];
    int b = blockIdx.x;
    int tid = threadIdx.x;

    float mx = -1e30f;
    for (int s = tid; s < SRC; s += 256) {
        float v = g_part[0][b][s] + g_part[1][b][s] + g_part[2][b][s] + g_part[3][b][s];
        sv[s] = v;
        mx = fmaxf(mx, v);
    }
    red[tid] = mx;
    __syncthreads();
    for (int st = 128; st > 0; st >>= 1) {
        if (tid < st) red[tid] = fmaxf(red[tid], red[tid + st]);
        __syncthreads();
    }
    mx = red[0];
    __syncthreads();

    float sum = 0.f;
    for (int s = tid; s < SRC; s += 256) {
        float e = expf(sv[s] - mx);
        sv[s] = e;
        sum += e;
    }
    red[tid] = sum;
    __syncthreads();
    for (int st = 128; st > 0; st >>= 1) {
        if (tid < st) red[tid] += red[tid + st];
        __syncthreads();
    }
    float inv = 1.0f / red[0];
    __syncthreads();

    for (int s = tid; s < SRC; s += 256) {
        out[(size_t)b * SRC + s] = sv[s] * inv;
    }
}

// ---------------- launch ----------------
extern "C" void kernel_launch(void* const* d_in, const int* in_sizes, int n_in,
                              void* d_out, int out_size) {
    const float* h    = (const float*)d_in[0];   // [1, 64, 512]
    const float* enc  = (const float*)d_in[1];   // [64, 2048, 512]
    const float* W1w  = (const float*)d_in[2];   // [512, 512]
    const float* W1b  = (const float*)d_in[3];   // [512]
    const float* W2w  = (const float*)d_in[4];   // [512, 512]
    const float* W2b  = (const float*)d_in[5];   // [512]
    const float* Vw   = (const float*)d_in[6];   // [1, 512]
    // d_in[7] = V_b : softmax-invariant -> unused
    float* out = (float*)d_out;                  // [64, 2048]

    cudaFuncSetAttribute(attn_main_kernel,
                         cudaFuncAttributeMaxDynamicSharedMemorySize, SMEM_BYTES);

    prep_w_kernel<<<(HID * HID + 511) / 512, 512>>>(W1w);
    cbias_kernel<<<dim3(BATCH, 4), 128>>>(h, W2w, W2b, W1b);
    attn_main_kernel<<<dim3(4, SRC / 128, BATCH), 256, SMEM_BYTES>>>(enc, Vw);
    softmax_kernel<<<BATCH, 256>>>(out);
}